// round 14
// baseline (speedup 1.0000x reference)
#include <cuda_runtime.h>
#include <cstdint>

#define BB 2
#define PP 200000
#define QQ 100
#define ROWS_PER_WARP 16
#define FULLM 0xffffffffu

// Per-batch nonempty bitmask: 4 words x 32 bits cover 100 queries.
__device__ unsigned g_bits[BB][4];

__device__ __forceinline__ float fast_rcp(float d) {
    float r;
    asm("rcp.approx.f32 %0, %1;" : "=f"(r) : "f"(d));
    r = fmaf(fmaf(-d, r, 1.0f), r, r);
    return r;
}

// One compacted entry: v = s * sigmoid(x[col]); update running (M,pos) and S.
__device__ __forceinline__ void proc_entry(
    float2 te, const float* __restrict__ rp, int mypos,
    float& M, int& pos, float& S)
{
    int ci = __float_as_int(te.y);            // original column index
    float x = __ldg(rp + ci);
    float e = __expf(-fabsf(x));
    float num = (x < 0.0f) ? e : 1.0f;
    float sig = num * fast_rcp(1.0f + e);     // sigmoid, ~1-2 ulp (validated)
    float v = te.x * sig;                     // pad entries: s=-1e30 -> v huge neg
    S += __expf(v);                           // pad -> underflow to exactly 0
    if (v > M) { M = v; pos = mypos; }        // strict > keeps earliest pos
}

// ---------------------------------------------------------------------------
// Main kernel — warp-cooperative rows, NO smem staging / NO cp.async.
// Block = 256 threads = 8 warps; each warp owns 16 consecutive rows.
// Prologue (per block): ordered ballot compaction of kept queries into a
//   128-entry (score, idx) table, padded with (-1e30, 0); each lane hoists
//   its 4 table entries (rounds r*32+lane) into registers.
// Per row: lanes gather-load their kept columns (LDG within the 400B row),
//   compute v, then 5-round shfl_xor butterfly: (max, min-pos tiebreak, sum).
// Lane 0 stores ins-tmp (mid+1) and conf; sem is a host-side memset node.
// Nonempty bits: per-warp regs -> smem atomicOr -> 4 global atomicOr / block.
// ---------------------------------------------------------------------------
__global__ void __launch_bounds__(256) main_kernel(
    const float* __restrict__ logits,
    const float* __restrict__ masks,
    const unsigned char* __restrict__ pad,
    float* __restrict__ out)
{
    __shared__ float2 tbl[128];        // (score, orig_idx as float-bits)
    __shared__ int s_cnt[8];
    __shared__ unsigned blkbits[4];

    const int t = threadIdx.x;
    const int wid = t >> 5, lane = t & 31;
    const int b = blockIdx.y;
    const size_t gbase = (size_t)b * PP;

    if (t < 4) blkbits[t] = 0;

    // --- Prologue: keep/score + ordered compaction ------------------------
    bool kp = false; float sv = 0.0f;
    if (t < QQ) {
        float l0 = logits[(b * QQ + t) * 2 + 0];
        float l1 = logits[(b * QQ + t) * 2 + 1];
        sv = fmaxf(l0, l1);
        kp = !(l1 > l0);                 // argmax first-tie -> label 0 (kept)
    }
    unsigned bal = __ballot_sync(FULLM, kp);
    if (lane == 0) s_cnt[wid] = __popc(bal);
    __syncthreads();
    int woff = 0, nk = 0;
    #pragma unroll
    for (int w = 0; w < 8; w++) {
        int c = s_cnt[w];
        if (w < wid) woff += c;
        nk += c;
    }
    if (kp) {
        int p = woff + __popc(bal & ((1u << lane) - 1u));
        tbl[p] = make_float2(sv, __int_as_float(t));
    }
    if (t >= nk && t < 128) tbl[t] = make_float2(-1e30f, __int_as_float(0));
    __syncthreads();

    const int nkr = (nk > 0) ? ((nk + 31) >> 5) : 1;   // rounds: 1..4

    // Hoist each lane's table entries to registers.
    const float2 t0 = tbl[lane];
    const float2 t1 = tbl[32 + lane];
    const float2 t2 = tbl[64 + lane];
    const float2 t3 = tbl[96 + lane];

    // --- Row loop ----------------------------------------------------------
    const int row0 = (blockIdx.x * 8 + wid) * ROWS_PER_WARP;
    unsigned mb0 = 0, mb1 = 0, mb2 = 0, mb3 = 0;       // lane0's bit words

    #pragma unroll 2
    for (int r = 0; r < ROWS_PER_WARP; r++) {
        int row = row0 + r;
        int rc = (row < PP) ? row : (PP - 1);
        const float* rp = masks + (gbase + (size_t)rc) * QQ;

        float M = -3.4e38f; int pos = 0; float S = 0.0f;
        proc_entry(t0, rp, lane, M, pos, S);
        if (nkr > 1) proc_entry(t1, rp, 32 + lane, M, pos, S);
        if (nkr > 2) proc_entry(t2, rp, 64 + lane, M, pos, S);
        if (nkr > 3) proc_entry(t3, rp, 96 + lane, M, pos, S);

        // Butterfly reduce: (max, min-pos tiebreak) + sum. All lanes converge.
        #pragma unroll
        for (int o = 16; o > 0; o >>= 1) {
            float Mo = __shfl_xor_sync(FULLM, M, o);
            int   po = __shfl_xor_sync(FULLM, pos, o);
            float So = __shfl_xor_sync(FULLM, S, o);
            S += So;
            if (Mo > M || (Mo == M && po < pos)) { M = Mo; pos = po; }
        }

        if (lane == 0 && row < PP) {
            float2 te = tbl[pos];
            float smid = te.x;
            int   mid  = __float_as_int(te.y);
            float sig_mid = M * fast_rcp(smid);
            bool validp = (nk > 0) && (sig_mid >= 1e-3f) &&
                          (pad[gbase + row] == 0);
            size_t base = gbase + row;
            out[(size_t)BB * PP + base] = validp ? (float)(mid + 1) : 0.0f;
            out[(size_t)2 * BB * PP + base] = __expf(M) * fast_rcp(S);
            if (validp) {
                int w = mid >> 5;
                unsigned bit = 1u << (mid & 31);
                mb0 |= (w == 0) ? bit : 0u;
                mb1 |= (w == 1) ? bit : 0u;
                mb2 |= (w == 2) ? bit : 0u;
                mb3 |= (w == 3) ? bit : 0u;
            }
        }
    }

    // --- Flags: warp -> block smem -> global -------------------------------
    if (lane == 0) {
        if (mb0) atomicOr(&blkbits[0], mb0);
        if (mb1) atomicOr(&blkbits[1], mb1);
        if (mb2) atomicOr(&blkbits[2], mb2);
        if (mb3) atomicOr(&blkbits[3], mb3);
    }
    __syncthreads();
    if (t < 4 && blkbits[t]) atomicOr(&g_bits[b][t], blkbits[t]);
}

// ---------------------------------------------------------------------------
// Remap kernel: seg_id(q) = prefix-popcount of g_bits. Output float4 load
// issued first so DRAM latency hides behind the (tiny) setup.
// ---------------------------------------------------------------------------
__global__ void __launch_bounds__(256) remap_kernel(float* __restrict__ out) {
    __shared__ unsigned sw[BB][4];
    __shared__ int      sp[BB][4];     // exclusive word-prefix popcounts
    const int t = threadIdx.x;
    const int i = blockIdx.x * 256 + t;                // one float4 per thread
    const int i0 = i * 4;
    const bool act = (i0 < BB * PP);
    float4* p4 = reinterpret_cast<float4*>(out + (size_t)BB * PP) + i;
    float4 v = make_float4(0.f, 0.f, 0.f, 0.f);
    if (act) v = *p4;                                  // in flight during setup

    if (t < BB * 4) sw[t >> 2][t & 3] = g_bits[t >> 2][t & 3];
    __syncthreads();
    if (t < BB) {
        int run = 0;
        #pragma unroll
        for (int w = 0; w < 4; w++) { sp[t][w] = run; run += __popc(sw[t][w]); }
    }
    __syncthreads();

    if (act) {
        const int b = (i0 >= PP) ? 1 : 0;              // PP % 4 == 0
        float r[4] = {v.x, v.y, v.z, v.w};
        #pragma unroll
        for (int e = 0; e < 4; e++) {
            if (r[e] != 0.0f) {
                int q = (int)r[e] - 1;                 // winning query index
                int w = q >> 5;
                unsigned m = sw[b][w] & (0xffffffffu >> (31 - (q & 31)));
                r[e] = (float)(sp[b][w] + __popc(m));  // inclusive prefix
            }
        }
        *p4 = make_float4(r[0], r[1], r[2], r[3]);
    }
}

extern "C" void kernel_launch(void* const* d_in, const int* in_sizes, int n_in,
                              void* d_out, int out_size) {
    const float* logits = (const float*)d_in[0];
    const float* masks  = (const float*)d_in[1];
    const unsigned char* pad = (const unsigned char*)d_in[2];
    float* out = (float*)d_out;

    // Zero the bitmask scratch and the sem output region (memset nodes).
    void* bits_ptr = nullptr;
    cudaGetSymbolAddress(&bits_ptr, g_bits);
    cudaMemsetAsync(bits_ptr, 0, sizeof(unsigned) * BB * 4, 0);
    cudaMemsetAsync(out, 0, (size_t)BB * PP * sizeof(float), 0);   // sem == 0

    // 8 warps/block * 16 rows/warp = 128 rows/block.
    dim3 grid((PP + 127) / 128, BB);
    main_kernel<<<grid, 256>>>(logits, masks, pad, out);

    remap_kernel<<<(BB * PP / 4 + 255) / 256, 256>>>(out);
}

// round 15
// speedup vs baseline: 2.5190x; 2.5190x over previous
#include <cuda_runtime.h>
#include <cstdint>

#define BB 2
#define PP 200000
#define QQ 100
#define TILE 128          // points per CTA
#define TILE_BYTES (TILE * QQ * 4)   // 51200

// Per-batch nonempty bitmask: 4 words x 32 bits cover 100 queries.
// Zero-initialized at module load; remap_kernel self-cleans it every replay.
__device__ unsigned g_bits[BB][4];
__device__ unsigned g_tick;

__device__ __forceinline__ float fast_rcp(float d) {
    float r;
    asm("rcp.approx.f32 %0, %1;" : "=f"(r) : "f"(d));
    r = fmaf(fmaf(-d, r, 1.0f), r, r);
    return r;
}

// 16B-granule swizzle, applied identically at cp.async dst and gathered LDS.
__device__ __forceinline__ unsigned swz(unsigned byteoff) {
    return byteoff ^ ((byteoff >> 3) & 0x70u);
}

// ---------------------------------------------------------------------------
// Main kernel — EXACT R12 structure (best-known): one-shot CTA tile,
// cp.async whole tile issued first, CTA-wide wait, per-thread row compute.
// Numerics bit-identical to all passing rounds (rel_err must reproduce).
// ---------------------------------------------------------------------------
__global__ void __launch_bounds__(TILE) main_kernel(
    const float* __restrict__ logits,
    const float* __restrict__ masks,
    const unsigned char* __restrict__ pad,
    float* __restrict__ out)
{
    extern __shared__ float s_x[];                 // TILE*QQ floats, swizzled
    __shared__ __align__(16) int   kidx[112];
    __shared__ __align__(16) float ks[112];
    __shared__ int s_cnt[4];
    __shared__ int flags[QQ];

    const int t = threadIdx.x;
    const int b = blockIdx.y;
    const int tile0 = blockIdx.x * TILE;
    const size_t gbase = (size_t)b * PP;

    // --- Phase A: issue loads FIRST ---------------------------------------
    {
        const char* gsrc = reinterpret_cast<const char*>(masks)
                         + (gbase + (size_t)tile0) * (QQ * 4);
        unsigned sbase = (unsigned)__cvta_generic_to_shared(s_x);
        size_t avail = ((size_t)PP - tile0) * (QQ * 4);
        #pragma unroll
        for (int k = 0; k < 25; k++) {
            unsigned off = (unsigned)(k * TILE + t) * 16u;    // 0..51184
            unsigned so = sbase + swz(off);
            size_t go = (off < avail) ? (size_t)off : (avail - 16);
            asm volatile("cp.async.cg.shared.global [%0], [%1], 16;"
                         :: "r"(so), "l"(gsrc + go));
        }
        asm volatile("cp.async.commit_group;");
    }

    // --- Phase B: keep + ordered compaction (overlaps with loads) ---------
    if (t < QQ) flags[t] = 0;
    bool kp = false; float sv = 0.0f;
    if (t < QQ) {
        float l0 = logits[(b * QQ + t) * 2 + 0];
        float l1 = logits[(b * QQ + t) * 2 + 1];
        sv = fmaxf(l0, l1);
        kp = !(l1 > l0);                 // argmax first-tie -> label 0 (kept)
    }
    unsigned bal = __ballot_sync(0xffffffffu, kp);
    const int wid = t >> 5, lane = t & 31;
    if (lane == 0) s_cnt[wid] = __popc(bal);
    __syncthreads();
    int woff = 0;
    #pragma unroll
    for (int w = 0; w < 4; w++) if (w < wid) woff += s_cnt[w];
    const int nk  = s_cnt[0] + s_cnt[1] + s_cnt[2] + s_cnt[3];
    const int nk4 = (nk + 3) & ~3;
    if (kp) {
        int pos = woff + __popc(bal & ((1u << lane) - 1u));
        kidx[pos] = t; ks[pos] = sv;
    }
    if (t < nk4 - nk) {                  // pad: huge-negative v, exp -> 0
        kidx[nk + t] = 0; ks[nk + t] = -1e30f;
    }

    asm volatile("cp.async.wait_group 0;" ::: "memory");
    __syncthreads();

    // --- Phase C: compute --------------------------------------------------
    const int p = tile0 + t;
    const bool active = (p < PP);
    const int pc = active ? p : (PP - 1);
    const char* srow = reinterpret_cast<const char*>(s_x);
    const unsigned rowb = (unsigned)t * (QQ * 4);

    float M = -3.4e38f; int jm = 0;
    float S0 = 0.0f, S1 = 0.0f, S2 = 0.0f, S3 = 0.0f;
    const int4*   k4 = reinterpret_cast<const int4*>(kidx);
    const float4* s4 = reinterpret_cast<const float4*>(ks);

    for (int j4 = 0; j4 < (nk4 >> 2); j4++) {
        int4   ki = k4[j4];                            // broadcast LDS.128
        float4 ss = s4[j4];
        {   float x = *reinterpret_cast<const float*>(srow + swz(rowb + 4u * ki.x));
            float e = __expf(-fabsf(x));
            float num = (x < 0.0f) ? e : 1.0f;
            float sig = num * fast_rcp(1.0f + e);
            float v = ss.x * sig;
            S0 += __expf(v);
            if (v > M) { M = v; jm = 4 * j4 + 0; } }
        {   float x = *reinterpret_cast<const float*>(srow + swz(rowb + 4u * ki.y));
            float e = __expf(-fabsf(x));
            float num = (x < 0.0f) ? e : 1.0f;
            float sig = num * fast_rcp(1.0f + e);
            float v = ss.y * sig;
            S1 += __expf(v);
            if (v > M) { M = v; jm = 4 * j4 + 1; } }
        {   float x = *reinterpret_cast<const float*>(srow + swz(rowb + 4u * ki.z));
            float e = __expf(-fabsf(x));
            float num = (x < 0.0f) ? e : 1.0f;
            float sig = num * fast_rcp(1.0f + e);
            float v = ss.z * sig;
            S2 += __expf(v);
            if (v > M) { M = v; jm = 4 * j4 + 2; } }
        {   float x = *reinterpret_cast<const float*>(srow + swz(rowb + 4u * ki.w));
            float e = __expf(-fabsf(x));
            float num = (x < 0.0f) ? e : 1.0f;
            float sig = num * fast_rcp(1.0f + e);
            float v = ss.w * sig;
            S3 += __expf(v);
            if (v > M) { M = v; jm = 4 * j4 + 3; } }
    }
    float S = (S0 + S1) + (S2 + S3);

    int   mid  = kidx[jm];
    float smid = ks[jm];
    float sig_mid = M * fast_rcp(smid);
    bool validp = active && (nk > 0) && (sig_mid >= 1e-3f) &&
                  (pad[gbase + pc] == 0);

    if (validp) flags[mid] = 1;          // benign race: same value

    if (active) {
        size_t base = gbase + p;
        out[base] = 0.0f;                                               // sem
        out[(size_t)BB * PP + base] = validp ? (float)(mid + 1) : 0.0f; // tmp
        out[(size_t)2 * BB * PP + base] = __expf(M) * fast_rcp(S);      // conf
    }

    __syncthreads();
    // --- Epilogue: flags -> 4 ballot words -> 4 no-return atomics ---------
    {
        bool fp = (t < QQ) ? (flags[t] != 0) : false;
        unsigned word = __ballot_sync(0xffffffffu, fp);
        if (lane == 0 && word) atomicOr(&g_bits[b][wid], word);
    }
}

// ---------------------------------------------------------------------------
// Remap kernel: seg_id(q) = prefix-popcount of g_bits, then SELF-CLEAN:
// each block takes a ticket AFTER it has read g_bits; the last block zeroes
// g_bits and the ticket, so the next graph replay starts clean without a
// separate memset node (saves one ~3.5us launch).
// ---------------------------------------------------------------------------
__global__ void __launch_bounds__(256) remap_kernel(float* __restrict__ out) {
    __shared__ unsigned sw[BB][4];
    __shared__ int      sp[BB][4];     // exclusive word-prefix popcounts
    const int t = threadIdx.x;
    const int i = blockIdx.x * 256 + t;                // one float4 per thread
    const int i0 = i * 4;
    const bool act = (i0 < BB * PP);
    float4* p4 = reinterpret_cast<float4*>(out + (size_t)BB * PP) + i;
    float4 v = make_float4(0.f, 0.f, 0.f, 0.f);
    if (act) v = *p4;                                  // in flight during setup

    if (t < BB * 4) sw[t >> 2][t & 3] = g_bits[t >> 2][t & 3];
    __syncthreads();                     // all reads of g_bits complete
    // Ticket AFTER the read: last block to arrive resets the globals.
    if (t == 0) {
        unsigned tk = atomicAdd(&g_tick, 1u);
        if (tk == gridDim.x - 1) {
            __threadfence();
            #pragma unroll
            for (int w = 0; w < 4; w++) { g_bits[0][w] = 0; g_bits[1][w] = 0; }
            g_tick = 0;
        }
    }
    if (t < BB) {
        int run = 0;
        #pragma unroll
        for (int w = 0; w < 4; w++) { sp[t][w] = run; run += __popc(sw[t][w]); }
    }
    __syncthreads();

    if (act) {
        const int b = (i0 >= PP) ? 1 : 0;              // PP % 4 == 0
        float r[4] = {v.x, v.y, v.z, v.w};
        #pragma unroll
        for (int e = 0; e < 4; e++) {
            if (r[e] != 0.0f) {
                int q = (int)r[e] - 1;                 // winning query index
                int w = q >> 5;
                unsigned m = sw[b][w] & (0xffffffffu >> (31 - (q & 31)));
                r[e] = (float)(sp[b][w] + __popc(m));  // inclusive prefix
            }
        }
        *p4 = make_float4(r[0], r[1], r[2], r[3]);
    }
}

extern "C" void kernel_launch(void* const* d_in, const int* in_sizes, int n_in,
                              void* d_out, int out_size) {
    const float* logits = (const float*)d_in[0];
    const float* masks  = (const float*)d_in[1];
    const unsigned char* pad = (const unsigned char*)d_in[2];
    float* out = (float*)d_out;

    static bool attr_set = false;
    if (!attr_set) {
        cudaFuncSetAttribute(main_kernel,
                             cudaFuncAttributeMaxDynamicSharedMemorySize,
                             TILE_BYTES);
        attr_set = true;
    }

    // Only TWO graph nodes: main + remap (remap self-cleans g_bits/g_tick).
    dim3 grid((PP + TILE - 1) / TILE, BB);
    main_kernel<<<grid, TILE, TILE_BYTES>>>(logits, masks, pad, out);

    remap_kernel<<<(BB * PP / 4 + 255) / 256, 256>>>(out);
}